// round 6
// baseline (speedup 1.0000x reference)
#include <cuda_runtime.h>

#define NN 50000
#define NE 800000
#define NG 128
#define D  64
#define NL 4
#define BN_EPS 1e-5f

#define NBLK 148
#define TPB  768
#define NWARP (TPB / 32)          // 24
#define GSZ  (NBLK * TPB)
#define NPW  8
#define NGRP (NN / NPW)           // 6250 exact
#define CHK  338                  // ceil(NN / NBLK)

#define SMEM_W_BYTES   (2048 * 8)                     // 16384
#define SMEM_ROW_BYTES (NWARP * NPW * D * 4)          // 49152
#define SMEM_TOTAL     (SMEM_W_BYTES + SMEM_ROW_BYTES + 2 * D * 4)

typedef unsigned long long ull;

// ---------------- device scratch ----------------
__device__ int   g_deg[NN];
__device__ int   g_off[NN + 1];
__device__ int   g_cur[NN];
__device__ __align__(8) int2 g_edge[NE];      // {src, float_bits(w)}
__device__ __align__(16) float g_h[NN * D];
__device__ __align__(16) float g_t[NN * D];
__device__ float g_stats[NL * 4 * D];
__device__ float g_pool[(NL + 1) * NG * D];
__device__ int   g_gstart[NG + 1];
__device__ int   g_bsum[NBLK];
__device__ unsigned g_tick[8];
__device__ unsigned g_barcnt;
__device__ unsigned g_bargen;

// ---------------- f32x2 helpers ----------------
__device__ __forceinline__ ull ffma2(ull a, ull b, ull c) {
    ull d; asm("fma.rn.f32x2 %0, %1, %2, %3;" : "=l"(d) : "l"(a), "l"(b), "l"(c)); return d;
}
__device__ __forceinline__ ull fadd2(ull a, ull b) {
    ull d; asm("add.rn.f32x2 %0, %1, %2;" : "=l"(d) : "l"(a), "l"(b)); return d;
}
__device__ __forceinline__ ull fpack2(float lo, float hi) {
    ull d; asm("mov.b64 %0, {%1, %2};" : "=l"(d) : "f"(lo), "f"(hi)); return d;
}
__device__ __forceinline__ float2 funpack2(ull a) {
    float lo, hi; asm("mov.b64 {%0, %1}, %2;" : "=f"(lo), "=f"(hi) : "l"(a));
    return make_float2(lo, hi);
}

// ---------------- software grid barrier ----------------
__device__ __forceinline__ void gsync() {
    __syncthreads();
    if (threadIdx.x == 0) {
        unsigned gen = *(volatile unsigned*)&g_bargen;
        __threadfence();
        unsigned t = atomicAdd(&g_barcnt, 1u);
        if (t == NBLK - 1) {
            g_barcnt = 0;
            __threadfence();
            atomicAdd(&g_bargen, 1u);
        } else {
            while (*(volatile unsigned*)&g_bargen == gen) __nanosleep(64);
        }
        __threadfence();
    }
    __syncthreads();
}

// ---------------- graph pooling (block-wide, blocks < NG only) ----------------
__device__ __forceinline__ void pool_block(const float* __restrict__ h, int pidx, int g,
                                           float* scr) {
    const int tid = threadIdx.x, warp = tid >> 5, lane = tid & 31, f0 = lane * 2;
    const int n0 = g_gstart[g], n1 = g_gstart[g + 1];
    float2 acc = make_float2(0.f, 0.f);
    for (int n = n0 + warp; n < n1; n += NWARP) {
        float2 v = *(const float2*)(h + (size_t)n * D + f0);
        acc.x += v.x; acc.y += v.y;
    }
    scr[warp * D + f0] = acc.x;
    scr[warp * D + f0 + 1] = acc.y;
    __syncthreads();
    if (tid < D) {
        float s = 0.f;
        #pragma unroll
        for (int w2 = 0; w2 < NWARP; w2++) s += scr[w2 * D + tid];
        g_pool[((size_t)pidx * NG + g) * D + tid] = s;
    }
    __syncthreads();
}

__global__ __launch_bounds__(TPB, 1) void k_gin(
    const float* __restrict__ x, const float* __restrict__ w,
    const int* __restrict__ src, const int* __restrict__ dst,
    const int* __restrict__ gids, const float* __restrict__ epsv,
    const float* __restrict__ W1, const float* __restrict__ b1,
    const float* __restrict__ mbng, const float* __restrict__ mbnb,
    const float* __restrict__ W2, const float* __restrict__ b2,
    const float* __restrict__ bng, const float* __restrict__ bnb,
    const float* __restrict__ predW, const float* __restrict__ predb,
    float* __restrict__ out)
{
    extern __shared__ __align__(16) char smem[];
    ull*   sWp   = (ull*)smem;                               // 2048 ull
    float* srow  = (float*)(smem + SMEM_W_BYTES);            // NWARP*NPW*D
    float* s_red = (float*)(smem + SMEM_W_BYTES + SMEM_ROW_BYTES);

    const int tid = threadIdx.x, bid = blockIdx.x;
    const int gtid = bid * TPB + tid;
    const int warp = tid >> 5, lane = tid & 31;
    const int grp = lane >> 3, fo = (lane & 7) * 8;
    const int f0 = lane * 2;
    float* myrow = srow + warp * (NPW * D);

    // ---------- phase 0 ----------
    if (gtid < NN) g_deg[gtid] = 0;
    if (gtid < NL * 4 * D) g_stats[gtid] = 0.f;
    if (gtid < 8) g_tick[gtid] = 0u;
    if (bid == 0 && tid <= NG) {
        if (tid == NG) g_gstart[NG] = NN;
        else {
            int lo = 0, hi = NN;
            while (lo < hi) {
                int m = (lo + hi) >> 1;
                if (gids[m] < tid) lo = m + 1; else hi = m;
            }
            g_gstart[tid] = lo;
        }
    }
    gsync();

    // ---------- phase 1: degree histogram ----------
    for (int e = gtid; e < NE; e += GSZ) atomicAdd(&g_deg[dst[e]], 1);
    gsync();

    // ---------- phase 2a: block-local scan ----------
    int* s_scan = (int*)sWp;
    {
        int node = bid * CHK + tid;
        int dv = 0;
        if (tid < CHK && node < NN) dv = g_deg[node];
        if (tid < 512) s_scan[tid] = (tid < CHK) ? dv : 0;
        __syncthreads();
        for (int off = 1; off < 512; off <<= 1) {
            int v = 0;
            if (tid < 512 && tid >= off) v = s_scan[tid - off];
            __syncthreads();
            if (tid < 512) s_scan[tid] += v;
            __syncthreads();
        }
        if (tid < CHK && node < NN) g_off[node] = s_scan[tid] - dv;
        if (tid == 0) g_bsum[bid] = s_scan[511];
    }
    gsync();

    // ---------- phase 2b: scan block totals ----------
    {
        int v = 0;
        if (tid < 256) { v = (tid < NBLK) ? g_bsum[tid] : 0; s_scan[tid] = v; }
        __syncthreads();
        for (int off = 1; off < 256; off <<= 1) {
            int u = 0;
            if (tid < 256 && tid >= off) u = s_scan[tid - off];
            __syncthreads();
            if (tid < 256) s_scan[tid] += u;
            __syncthreads();
        }
        if (tid < 256) s_scan[256 + tid] = s_scan[tid] - v;
        __syncthreads();
        int prefix = s_scan[256 + bid];
        int node = bid * CHK + tid;
        if (tid < CHK && node < NN) {
            int o = g_off[node] + prefix;
            g_off[node] = o; g_cur[node] = o;
        }
        if (bid == 0 && tid == 0) g_off[NN] = s_scan[NBLK - 1];
    }
    gsync();

    // ---------- phase 3: scatter edges + pool0 ----------
    for (int e = gtid; e < NE; e += GSZ) {
        int dn = dst[e];
        int p = atomicAdd(&g_cur[dn], 1);
        g_edge[p] = make_int2(src[e], __float_as_int(w[e]));
    }
    if (bid < NG) pool_block(x, 0, bid, srow);
    gsync();

    // ---------- layers ----------
    for (int l = 0; l < NL; l++) {
        // ===== phase A: aggregate + GEMM1 + stats1 (+ pool_l for l>0) =====
        {
            const float* W1l = W1 + (size_t)l * D * D;
            for (int i = tid; i < 2048; i += TPB) {
                int k2 = i >> 6, f = i & 63;
                sWp[i] = fpack2(W1l[(2 * k2) * D + f], W1l[(2 * k2 + 1) * D + f]);
            }
            if (tid < 2 * D) s_red[tid] = 0.f;
            __syncthreads();
            if (l > 0 && bid < NG) pool_block(g_h, l, bid, srow);
            __syncthreads();

            const float* hin = (l == 0) ? x : g_h;
            const float ep1 = 1.0f + epsv[l];
            const ull ep2 = fpack2(ep1, ep1);
            float2 bb = *(const float2*)(b1 + (size_t)l * D + f0);
            float2 psum = make_float2(0.f, 0.f), psq = make_float2(0.f, 0.f);

            for (;;) {
                unsigned g = 0;
                if (lane == 0) g = atomicAdd(&g_tick[l], 1u);
                g = __shfl_sync(0xffffffffu, g, 0);
                if (g >= NGRP) break;
                const int base = (int)g * NPW;

                #pragma unroll 1
                for (int j = 0; j < NPW; j++) {
                    const int n = base + j;
                    const int e0 = g_off[n], e1 = g_off[n + 1];
                    ull a0 = 0, a1 = 0, a2 = 0, a3 = 0;
                    for (int eb = e0; eb < e1; eb += 32) {
                        const int cnt = min(32, e1 - eb);
                        int sv = 0; float wv = 0.f;
                        if (lane < cnt) {
                            int2 ed = g_edge[eb + lane];
                            sv = ed.x; wv = __int_as_float(ed.y);
                        }
                        #pragma unroll 2
                        for (int t = 0; t < cnt; t += 8) {
                            const int iA = t + grp, iB = t + 4 + grp;
                            int   sA = __shfl_sync(0xffffffffu, sv, iA & 31);
                            float wA = __shfl_sync(0xffffffffu, wv, iA & 31);
                            int   sB = __shfl_sync(0xffffffffu, sv, iB & 31);
                            float wB = __shfl_sync(0xffffffffu, wv, iB & 31);
                            const bool pA = iA < cnt, pB = iB < cnt;
                            ulonglong2 q0, q1, r0, r1;
                            if (pA) {
                                const float* hp = hin + (size_t)sA * D + fo;
                                q0 = *(const ulonglong2*)hp;
                                q1 = *(const ulonglong2*)(hp + 4);
                            }
                            if (pB) {
                                const float* hp = hin + (size_t)sB * D + fo;
                                r0 = *(const ulonglong2*)hp;
                                r1 = *(const ulonglong2*)(hp + 4);
                            }
                            if (pA) {
                                ull w2 = fpack2(wA, wA);
                                a0 = ffma2(q0.x, w2, a0); a1 = ffma2(q0.y, w2, a1);
                                a2 = ffma2(q1.x, w2, a2); a3 = ffma2(q1.y, w2, a3);
                            }
                            if (pB) {
                                ull w2 = fpack2(wB, wB);
                                a0 = ffma2(r0.x, w2, a0); a1 = ffma2(r0.y, w2, a1);
                                a2 = ffma2(r1.x, w2, a2); a3 = ffma2(r1.y, w2, a3);
                            }
                        }
                    }
                    a0 = fadd2(a0, __shfl_xor_sync(0xffffffffu, a0, 8));
                    a1 = fadd2(a1, __shfl_xor_sync(0xffffffffu, a1, 8));
                    a2 = fadd2(a2, __shfl_xor_sync(0xffffffffu, a2, 8));
                    a3 = fadd2(a3, __shfl_xor_sync(0xffffffffu, a3, 8));
                    a0 = fadd2(a0, __shfl_xor_sync(0xffffffffu, a0, 16));
                    a1 = fadd2(a1, __shfl_xor_sync(0xffffffffu, a1, 16));
                    a2 = fadd2(a2, __shfl_xor_sync(0xffffffffu, a2, 16));
                    a3 = fadd2(a3, __shfl_xor_sync(0xffffffffu, a3, 16));
                    if (grp == 0) {
                        const float* hp = hin + (size_t)n * D + fo;
                        ulonglong2 p0 = *(const ulonglong2*)hp;
                        ulonglong2 p1 = *(const ulonglong2*)(hp + 4);
                        ulonglong2 r0, r1;
                        r0.x = ffma2(p0.x, ep2, a0); r0.y = ffma2(p0.y, ep2, a1);
                        r1.x = ffma2(p1.x, ep2, a2); r1.y = ffma2(p1.y, ep2, a3);
                        *(ulonglong2*)(myrow + j * D + fo) = r0;
                        *(ulonglong2*)(myrow + j * D + fo + 4) = r1;
                    }
                }
                __syncwarp();

                // GEMM1: 8-node blocking, 16B weight loads + 16B h broadcasts
                ull acc0[NPW], acc1[NPW];
                #pragma unroll
                for (int j = 0; j < NPW; j++) { acc0[j] = 0; acc1[j] = 0; }
                #pragma unroll
                for (int k2 = 0; k2 < 32; k2 += 2) {
                    ulonglong2 w0 = *(const ulonglong2*)(sWp + k2 * D + f0);
                    ulonglong2 w1 = *(const ulonglong2*)(sWp + (k2 + 1) * D + f0);
                    #pragma unroll
                    for (int j = 0; j < NPW; j++) {
                        ulonglong2 h2 = *(const ulonglong2*)(myrow + j * D + 2 * k2);
                        acc0[j] = ffma2(h2.x, w0.x, acc0[j]);
                        acc1[j] = ffma2(h2.x, w0.y, acc1[j]);
                        acc0[j] = ffma2(h2.y, w1.x, acc0[j]);
                        acc1[j] = ffma2(h2.y, w1.y, acc1[j]);
                    }
                }
                #pragma unroll
                for (int j = 0; j < NPW; j++) {
                    float2 u0 = funpack2(acc0[j]), u1 = funpack2(acc1[j]);
                    float ax = u0.x + u0.y + bb.x;
                    float ay = u1.x + u1.y + bb.y;
                    *(float2*)(g_t + (size_t)(base + j) * D + f0) = make_float2(ax, ay);
                    psum.x += ax; psum.y += ay;
                    psq.x = fmaf(ax, ax, psq.x);
                    psq.y = fmaf(ay, ay, psq.y);
                }
                __syncwarp();
            }
            atomicAdd(&s_red[f0], psum.x);
            atomicAdd(&s_red[f0 + 1], psum.y);
            atomicAdd(&s_red[D + f0], psq.x);
            atomicAdd(&s_red[D + f0 + 1], psq.y);
            __syncthreads();
            if (tid < D) {
                atomicAdd(&g_stats[(l * 4 + 0) * D + tid], s_red[tid]);
                atomicAdd(&g_stats[(l * 4 + 1) * D + tid], s_red[D + tid]);
            }
        }
        gsync();

        // ===== phase B: BN1 + ReLU + GEMM2 + stats2 =====
        {
            const float* W2l = W2 + (size_t)l * D * D;
            for (int i = tid; i < 2048; i += TPB) {
                int k2 = i >> 6, f = i & 63;
                sWp[i] = fpack2(W2l[(2 * k2) * D + f], W2l[(2 * k2 + 1) * D + f]);
            }
            if (tid < 2 * D) s_red[tid] = 0.f;
            __syncthreads();

            const float invN = 1.0f / NN;
            const float* sum1 = g_stats + (l * 4 + 0) * D;
            const float* sq1  = g_stats + (l * 4 + 1) * D;
            float mu0 = sum1[f0] * invN, mu1 = sum1[f0 + 1] * invN;
            float v0 = sq1[f0] * invN - mu0 * mu0;
            float v1 = sq1[f0 + 1] * invN - mu1 * mu1;
            float sc0 = mbng[l * D + f0] * rsqrtf(v0 + BN_EPS);
            float sc1 = mbng[l * D + f0 + 1] * rsqrtf(v1 + BN_EPS);
            float sh0 = mbnb[l * D + f0] - mu0 * sc0;
            float sh1 = mbnb[l * D + f0 + 1] - mu1 * sc1;
            float2 bb = *(const float2*)(b2 + (size_t)l * D + f0);
            float2 psum = make_float2(0.f, 0.f), psq = make_float2(0.f, 0.f);

            for (;;) {
                unsigned g = 0;
                if (lane == 0) g = atomicAdd(&g_tick[4 + l], 1u);
                g = __shfl_sync(0xffffffffu, g, 0);
                if (g >= NGRP) break;
                const int base = (int)g * NPW;

                #pragma unroll
                for (int j = 0; j < NPW; j++) {
                    float2 t2 = *(const float2*)(g_t + (size_t)(base + j) * D + f0);
                    float u0 = fmaxf(fmaf(t2.x, sc0, sh0), 0.f);
                    float u1 = fmaxf(fmaf(t2.y, sc1, sh1), 0.f);
                    *(float2*)(myrow + j * D + f0) = make_float2(u0, u1);
                }
                __syncwarp();

                ull acc0[NPW], acc1[NPW];
                #pragma unroll
                for (int j = 0; j < NPW; j++) { acc0[j] = 0; acc1[j] = 0; }
                #pragma unroll
                for (int k2 = 0; k2 < 32; k2 += 2) {
                    ulonglong2 w0 = *(const ulonglong2*)(sWp + k2 * D + f0);
                    ulonglong2 w1 = *(const ulonglong2*)(sWp + (k2 + 1) * D + f0);
                    #pragma unroll
                    for (int j = 0; j < NPW; j++) {
                        ulonglong2 h2 = *(const ulonglong2*)(myrow + j * D + 2 * k2);
                        acc0[j] = ffma2(h2.x, w0.x, acc0[j]);
                        acc1[j] = ffma2(h2.x, w0.y, acc1[j]);
                        acc0[j] = ffma2(h2.y, w1.x, acc0[j]);
                        acc1[j] = ffma2(h2.y, w1.y, acc1[j]);
                    }
                }
                #pragma unroll
                for (int j = 0; j < NPW; j++) {
                    float2 u0 = funpack2(acc0[j]), u1 = funpack2(acc1[j]);
                    float ax = u0.x + u0.y + bb.x;
                    float ay = u1.x + u1.y + bb.y;
                    *(float2*)(g_t + (size_t)(base + j) * D + f0) = make_float2(ax, ay);
                    psum.x += ax; psum.y += ay;
                    psq.x = fmaf(ax, ax, psq.x);
                    psq.y = fmaf(ay, ay, psq.y);
                }
                __syncwarp();
            }
            atomicAdd(&s_red[f0], psum.x);
            atomicAdd(&s_red[f0 + 1], psum.y);
            atomicAdd(&s_red[D + f0], psq.x);
            atomicAdd(&s_red[D + f0 + 1], psq.y);
            __syncthreads();
            if (tid < D) {
                atomicAdd(&g_stats[(l * 4 + 2) * D + tid], s_red[tid]);
                atomicAdd(&g_stats[(l * 4 + 3) * D + tid], s_red[D + tid]);
            }
        }
        gsync();

        // ===== phase C: outer BN + ReLU -> g_h =====
        {
            if (tid < D) {
                const float invN = 1.0f / NN;
                float mu = g_stats[(l * 4 + 2) * D + tid] * invN;
                float var = g_stats[(l * 4 + 3) * D + tid] * invN - mu * mu;
                float sc = bng[l * D + tid] * rsqrtf(var + BN_EPS);
                s_red[tid] = sc;
                s_red[D + tid] = bnb[l * D + tid] - mu * sc;
            }
            __syncthreads();
            for (int i4 = gtid; i4 < NN * (D / 4); i4 += GSZ) {
                int fb = (i4 & 15) * 4;
                float4 t = *(const float4*)(g_t + (size_t)i4 * 4);
                float4 o;
                o.x = fmaxf(fmaf(t.x, s_red[fb + 0], s_red[D + fb + 0]), 0.f);
                o.y = fmaxf(fmaf(t.y, s_red[fb + 1], s_red[D + fb + 1]), 0.f);
                o.z = fmaxf(fmaf(t.z, s_red[fb + 2], s_red[D + fb + 2]), 0.f);
                o.w = fmaxf(fmaf(t.w, s_red[fb + 3], s_red[D + fb + 3]), 0.f);
                *(float4*)(g_h + (size_t)i4 * 4) = o;
            }
        }
        gsync();
    }

    // ---------- final pool ----------
    if (bid < NG) pool_block(g_h, NL, bid, srow);
    gsync();

    // ---------- score ----------
    for (int idx = gtid; idx < NG * 16; idx += GSZ) {
        int g = idx >> 4, o = idx & 15;
        float s = 0.f;
        #pragma unroll
        for (int l = 0; l < NL + 1; l++) {
            s += predb[l * 16 + o];
            const float* P  = g_pool + ((size_t)l * NG + g) * D;
            const float* Wp = predW + (size_t)l * D * 16;
            #pragma unroll
            for (int d = 0; d < D; d++) s = fmaf(P[d], Wp[d * 16 + o], s);
        }
        out[idx] = s;
    }
}

// ---------------- launch ----------------
extern "C" void kernel_launch(void* const* d_in, const int* in_sizes, int n_in,
                              void* d_out, int out_size)
{
    const float* x    = (const float*)d_in[0];
    const float* w    = (const float*)d_in[1];
    const int*   src  = (const int*)d_in[2];
    const int*   dst  = (const int*)d_in[3];
    const int*   gids = (const int*)d_in[4];
    const float* eps  = (const float*)d_in[5];
    const float* W1   = (const float*)d_in[6];
    const float* b1   = (const float*)d_in[7];
    const float* mbng = (const float*)d_in[8];
    const float* mbnb = (const float*)d_in[9];
    const float* W2   = (const float*)d_in[10];
    const float* b2   = (const float*)d_in[11];
    const float* bng  = (const float*)d_in[12];
    const float* bnb  = (const float*)d_in[13];
    const float* predW = (const float*)d_in[14];
    const float* predb = (const float*)d_in[15];
    float* out = (float*)d_out;

    cudaFuncSetAttribute(k_gin, cudaFuncAttributeMaxDynamicSharedMemorySize, SMEM_TOTAL);
    k_gin<<<NBLK, TPB, SMEM_TOTAL>>>(x, w, src, dst, gids, eps, W1, b1, mbng, mbnb,
                                     W2, b2, bng, bnb, predW, predb, out);
}